// round 1
// baseline (speedup 1.0000x reference)
#include <cuda_runtime.h>

#define F_DIM 16384
#define N_BINS 128
#define NT_A 256
#define N_ROWS 4096
#define N_OUT 64
#define N_FEATS 257          // 2*BINS + 1
#define SCR_STRIDE 132       // 128 counts + mn + width (+pad)

// Static device scratch (allocation-free): per-row [counts(128), mn, width]
__device__ float g_scratch[N_ROWS * SCR_STRIDE];

__device__ __forceinline__ float f_inf() { return __int_as_float(0x7f800000); }

// ---------------------------------------------------------------------------
// Kernel A: one CTA per row. Stage row in SMEM, min/max reduce, private
// per-thread u8 histograms in a conflict-free layout, packed reduce.
// SMEM: [0,64K) row data | [64K,96K) hist (128 bins x 256 thread-bytes)
//       | [96K, +256B) reduction scratch
// ---------------------------------------------------------------------------
__global__ __launch_bounds__(NT_A) void hist_kernel(const float* __restrict__ x) {
    extern __shared__ unsigned char smem[];
    float* s_data = (float*)smem;                          // 65536 B
    unsigned char* s_hist = smem + 65536;                  // 32768 B
    float* s_red = (float*)(smem + 65536 + 32768);         // 64 floats

    const int tid = threadIdx.x;
    const int row = blockIdx.x;
    const float4* __restrict__ xr = (const float4*)(x + (size_t)row * F_DIM);
    float4* sd4 = (float4*)s_data;

    // ---- Phase 1: load row (streaming), track min/max, stage to SMEM ----
    float mn = f_inf(), mx = -f_inf();
#pragma unroll 8
    for (int i = 0; i < 16; i++) {
        float4 v = __ldcs(xr + tid + i * NT_A);
        sd4[tid + i * NT_A] = v;
        mn = fminf(mn, fminf(fminf(v.x, v.y), fminf(v.z, v.w)));
        mx = fmaxf(mx, fmaxf(fmaxf(v.x, v.y), fmaxf(v.z, v.w)));
    }
#pragma unroll
    for (int o = 16; o > 0; o >>= 1) {
        mn = fminf(mn, __shfl_xor_sync(0xFFFFFFFFu, mn, o));
        mx = fmaxf(mx, __shfl_xor_sync(0xFFFFFFFFu, mx, o));
    }
    const int wid = tid >> 5;
    if ((tid & 31) == 0) { s_red[wid] = mn; s_red[8 + wid] = mx; }

    // Zero histogram (each thread owns 128 bytes -> 8 x uint4)
    {
        uint4* hz = (uint4*)(s_hist + tid * 128);
        uint4 z = make_uint4(0u, 0u, 0u, 0u);
#pragma unroll
        for (int i = 0; i < 8; i++) hz[i] = z;
    }
    __syncthreads();

    // Every thread redundantly reduces the 8 warp partials (avoids 2nd sync)
    mn = s_red[0]; mx = s_red[8];
#pragma unroll
    for (int i = 1; i < 8; i++) { mn = fminf(mn, s_red[i]); mx = fmaxf(mx, s_red[8 + i]); }
    const float width = mx - mn;
    const float scale = 128.0f / (width == 0.0f ? 1.0f : width);   // matches jnp where()

    // ---- Phase 2: histogram. Counter for (bin, t) at byte
    //   s_hist[bin*256 + 4*(t & 63) + (t >> 6)]
    // => bank = t & 31 for every lane: conflict-free byte RMW, no atomics.
    unsigned char* hbase = s_hist + ((tid & 63) << 2) + (tid >> 6);

#define HIST_UPDATE(val)                                                     \
    {                                                                        \
        float f_ = fminf(((val) - mn) * scale, 127.0f);                      \
        int b_ = (int)f_; /* f_ >= 0 always, trunc == floor */               \
        hbase[b_ << 8]++;                                                    \
    }

#pragma unroll 4
    for (int i = 0; i < 16; i++) {
        float4 v = sd4[tid + i * NT_A];
        HIST_UPDATE(v.x);
        HIST_UPDATE(v.y);
        HIST_UPDATE(v.z);
        HIST_UPDATE(v.w);
    }
#undef HIST_UPDATE
    __syncthreads();

    // ---- Reduce: bin = tid>>1, each of the pair sums 32 of 64 words.
    // Packed byte sums in two u32 accumulators (u16 fields, max 32*64 < 65536).
    const unsigned int* h32 = (const unsigned int*)s_hist;
    const int bin = tid >> 1;
    const int base_w = (bin << 6) + ((tid & 1) << 5);
    const int r0 = tid & 31;  // lane rotation -> distinct banks every step
    unsigned int lo = 0, hi = 0;
#pragma unroll
    for (int j = 0; j < 32; j++) {
        unsigned int w = h32[base_w + ((r0 + j) & 31)];
        lo += w & 0x00FF00FFu;
        hi += (w >> 8) & 0x00FF00FFu;
    }
    unsigned int s = (lo & 0xFFFFu) + (lo >> 16) + (hi & 0xFFFFu) + (hi >> 16);
    s += __shfl_xor_sync(0xFFFFFFFFu, s, 1);   // combine the two halves

    float* scr = g_scratch + (size_t)row * SCR_STRIDE;
    if ((tid & 1) == 0) scr[bin] = (float)s;
    if (tid == 0) { scr[128] = mn; scr[129] = width; }
}

// ---------------------------------------------------------------------------
// Kernel B: 4 rows x 64 outputs per CTA. W staged in SMEM (L2-resident).
// out[r][o] = (1/F) * sum_b cnt[b] W[o][b]
//           + mn * sum_j W[o][128+j] + width * sum_j (j/128) W[o][128+j]
//           + bias[o]
// ---------------------------------------------------------------------------
#define NT_B 256
__global__ __launch_bounds__(NT_B) void out_kernel(const float* __restrict__ W,
                                                   const float* __restrict__ bias,
                                                   float* __restrict__ out) {
    extern __shared__ float sm[];
    float* sW = sm;                       // 64*257 = 16448
    float* sB = sm + 16448;               // 64
    float* sC = sm + 16448 + 64;          // 4*132 = 528

    const int tid = threadIdx.x;
    const int r0 = blockIdx.x * 4;

    for (int i = tid; i < N_OUT * N_FEATS; i += NT_B) sW[i] = W[i];
    if (tid < N_OUT) sB[tid] = bias[tid];
    for (int i = tid; i < 4 * SCR_STRIDE; i += NT_B)
        sC[i] = g_scratch[(size_t)r0 * SCR_STRIDE + i];
    __syncthreads();

    const int o = tid & 63;
    const int lr = tid >> 6;
    const float* w = sW + o * N_FEATS;           // bank = (o+b)&31: conflict-free
    const float* c = sC + lr * SCR_STRIDE;       // broadcast within warp
    const float mnv = c[128];
    const float wdv = c[129];

    float acc_h = 0.0f;
#pragma unroll 8
    for (int b = 0; b < N_BINS; b++) acc_h = fmaf(c[b], w[b], acc_h);

    float acc0 = 0.0f, acc1 = 0.0f, tj = 0.0f;
#pragma unroll 8
    for (int j = 0; j <= N_BINS; j++) {          // 129 boundary weights
        float wv = w[N_BINS + j];
        acc0 += wv;
        acc1 = fmaf(tj, wv, acc1);
        tj += 0.0078125f;                        // exact j/128 throughout
    }

    float res = fmaf(acc_h, 1.0f / 16384.0f,
                     fmaf(mnv, acc0, fmaf(wdv, acc1, sB[o])));
    out[(size_t)r0 * N_OUT + tid] = res;         // coalesced: r0*64 + tid
}

// ---------------------------------------------------------------------------
extern "C" void kernel_launch(void* const* d_in, const int* in_sizes, int n_in,
                              void* d_out, int out_size) {
    const float* x = (const float*)d_in[0];
    const float* W = (const float*)d_in[1];
    const float* b = (const float*)d_in[2];
    float* out = (float*)d_out;

    const int smemA = 65536 + 32768 + 64 * 4;            // 98560 B
    const int smemB = (16448 + 64 + 528) * 4;            // 68160 B
    cudaFuncSetAttribute(hist_kernel, cudaFuncAttributeMaxDynamicSharedMemorySize, smemA);
    cudaFuncSetAttribute(out_kernel, cudaFuncAttributeMaxDynamicSharedMemorySize, smemB);

    hist_kernel<<<N_ROWS, NT_A, smemA>>>(x);
    out_kernel<<<N_ROWS / 4, NT_B, smemB>>>(W, b, out);
}

// round 2
// speedup vs baseline: 1.2841x; 1.2841x over previous
#include <cuda_runtime.h>

#define F_DIM 16384
#define N_BINS 128
#define NT_A 256
#define N_ROWS 4096
#define N_OUT 64
#define N_FEATS 257          // 2*BINS + 1
#define SCR_STRIDE 132       // 128 counts + mn + width (+pad)

// Static device scratch (allocation-free): per-row [counts(128), mn, width]
__device__ float g_scratch[N_ROWS * SCR_STRIDE];

__device__ __forceinline__ float f_inf() { return __int_as_float(0x7f800000); }

// ---------------------------------------------------------------------------
// Kernel A: one CTA per row. Half the row staged in SMEM, half kept in
// registers. Per-thread private u8 histograms in a conflict-free layout.
// SMEM: [0,32K) half row | [32K,64K) hist (128 bins x 256 thread-bytes)
//       | [64K, +64 floats) reduction scratch
// 65.8 KB/CTA -> 3 CTAs/SM (24 warps) so load/bin/reduce phases of different
// CTAs overlap and DRAM stays saturated.
// ---------------------------------------------------------------------------
__global__ __launch_bounds__(NT_A, 3) void hist_kernel(const float* __restrict__ x) {
    extern __shared__ unsigned char smem[];
    float4* sd4 = (float4*)smem;                           // 32768 B
    unsigned char* s_hist = smem + 32768;                  // 32768 B
    float* s_red = (float*)(smem + 65536);                 // 64 floats

    const int tid = threadIdx.x;
    const int row = blockIdx.x;
    const float4* __restrict__ xr = (const float4*)(x + (size_t)row * F_DIM);

    // ---- Phase 1: load row. First 8 iters -> SMEM, last 8 stay in regs ----
    float mn = f_inf(), mx = -f_inf();
    float4 rv[8];
#pragma unroll
    for (int i = 0; i < 8; i++) {
        float4 v = __ldcg(xr + tid + i * NT_A);
        sd4[tid + i * NT_A] = v;
        mn = fminf(mn, fminf(fminf(v.x, v.y), fminf(v.z, v.w)));
        mx = fmaxf(mx, fmaxf(fmaxf(v.x, v.y), fmaxf(v.z, v.w)));
    }
#pragma unroll
    for (int i = 0; i < 8; i++) {
        float4 v = __ldcg(xr + tid + (8 + i) * NT_A);
        rv[i] = v;
        mn = fminf(mn, fminf(fminf(v.x, v.y), fminf(v.z, v.w)));
        mx = fmaxf(mx, fmaxf(fmaxf(v.x, v.y), fmaxf(v.z, v.w)));
    }
#pragma unroll
    for (int o = 16; o > 0; o >>= 1) {
        mn = fminf(mn, __shfl_xor_sync(0xFFFFFFFFu, mn, o));
        mx = fmaxf(mx, __shfl_xor_sync(0xFFFFFFFFu, mx, o));
    }
    const int wid = tid >> 5;
    if ((tid & 31) == 0) { s_red[wid] = mn; s_red[8 + wid] = mx; }

    // Zero histogram (each thread zeroes a contiguous 128 B chunk)
    {
        uint4* hz = (uint4*)(s_hist + tid * 128);
        uint4 z = make_uint4(0u, 0u, 0u, 0u);
#pragma unroll
        for (int i = 0; i < 8; i++) hz[i] = z;
    }
    __syncthreads();

    // Every thread redundantly reduces the 8 warp partials (no 2nd sync)
    mn = s_red[0]; mx = s_red[8];
#pragma unroll
    for (int i = 1; i < 8; i++) { mn = fminf(mn, s_red[i]); mx = fmaxf(mx, s_red[8 + i]); }
    const float width = mx - mn;
    const float scale = 128.0f / (width == 0.0f ? 1.0f : width);   // matches jnp where()

    // ---- Phase 2: histogram. Counter for (bin, t) at byte
    //   s_hist[bin*256 + 4*(t & 63) + (t >> 6)]  => bank = t & 31 for every
    // lane: conflict-free byte RMW, no atomics. Max 64 counts -> fits u8.
    unsigned char* hbase = s_hist + ((tid & 63) << 2) + (tid >> 6);

#define HIST_UPDATE(val)                                                     \
    {                                                                        \
        float f_ = fminf(((val) - mn) * scale, 127.0f);                      \
        int b_ = (int)f_; /* f_ >= 0 always, trunc == floor */               \
        hbase[b_ << 8]++;                                                    \
    }

    // Register half first (no loads needed)
#pragma unroll
    for (int i = 0; i < 8; i++) {
        HIST_UPDATE(rv[i].x); HIST_UPDATE(rv[i].y);
        HIST_UPDATE(rv[i].z); HIST_UPDATE(rv[i].w);
    }
    // SMEM half
#pragma unroll 4
    for (int i = 0; i < 8; i++) {
        float4 v = sd4[tid + i * NT_A];
        HIST_UPDATE(v.x); HIST_UPDATE(v.y);
        HIST_UPDATE(v.z); HIST_UPDATE(v.w);
    }
#undef HIST_UPDATE
    __syncthreads();

    // ---- Reduce: bin = tid>>1, each of the pair sums 32 of 64 words.
    // Packed byte sums in u16 fields (max 32*64 < 65536), lane-rotated banks.
    const unsigned int* h32 = (const unsigned int*)s_hist;
    const int bin = tid >> 1;
    const int base_w = (bin << 6) + ((tid & 1) << 5);
    const int r0 = tid & 31;
    unsigned int lo = 0, hi = 0;
#pragma unroll
    for (int j = 0; j < 32; j++) {
        unsigned int w = h32[base_w + ((r0 + j) & 31)];
        lo += w & 0x00FF00FFu;
        hi += (w >> 8) & 0x00FF00FFu;
    }
    unsigned int s = (lo & 0xFFFFu) + (lo >> 16) + (hi & 0xFFFFu) + (hi >> 16);
    s += __shfl_xor_sync(0xFFFFFFFFu, s, 1);

    float* scr = g_scratch + (size_t)row * SCR_STRIDE;
    if ((tid & 1) == 0) scr[bin] = (float)s;
    if (tid == 0) { scr[128] = mn; scr[129] = width; }
}

// ---------------------------------------------------------------------------
// Kernel B: 16 rows x 64 outputs per CTA (256 CTAs). W staged once per CTA.
// Boundary half decomposed: out[r][o] = cnt.Wh[o]/F + mn*S0[o] + wd*S1[o] + b[o]
// with S0[o] = sum_j W[o][128+j], S1[o] = sum_j (j/128) W[o][128+j] computed
// once per CTA. Main dot: w cached in 16-reg chunks reused over 4 rows,
// counts read as broadcast float4.
// ---------------------------------------------------------------------------
#define NT_B 256
#define ROWS_B 16
__global__ __launch_bounds__(NT_B, 2) void out_kernel(const float* __restrict__ W,
                                                      const float* __restrict__ bias,
                                                      float* __restrict__ out) {
    extern __shared__ float sm[];
    float* sW = sm;                          // 64*257 = 16448
    float* sB = sm + 16448;                  // 64
    float* sS0 = sm + 16448 + 64;            // 64
    float* sS1 = sm + 16448 + 128;           // 64
    float* sC = sm + 16448 + 192;            // 16*132 = 2112

    const int tid = threadIdx.x;
    const int r0 = blockIdx.x * ROWS_B;

    for (int i = tid; i < N_OUT * N_FEATS; i += NT_B) sW[i] = W[i];
    if (tid < N_OUT) sB[tid] = bias[tid];
    for (int i = tid; i < ROWS_B * SCR_STRIDE; i += NT_B)
        sC[i] = g_scratch[(size_t)r0 * SCR_STRIDE + i];
    __syncthreads();

    // Per-output boundary sums (64 threads, once per CTA)
    if (tid < N_OUT) {
        const float* wb = sW + tid * N_FEATS + N_BINS;
        float s0 = 0.0f, s1 = 0.0f, tj = 0.0f;
#pragma unroll 8
        for (int j = 0; j <= N_BINS; j++) {
            float wv = wb[j];
            s0 += wv;
            s1 = fmaf(tj, wv, s1);
            tj += 0.0078125f;                // exact j/128 throughout
        }
        sS0[tid] = s0; sS1[tid] = s1;
    }
    __syncthreads();

    const int o = tid & 63;
    const int rg = tid >> 6;                 // 4 row-groups x 4 rows
    const float* w = sW + o * N_FEATS;       // bank (o+b)&31: conflict-free

    float acc0 = 0.0f, acc1 = 0.0f, acc2 = 0.0f, acc3 = 0.0f;
#pragma unroll
    for (int ch = 0; ch < 8; ch++) {         // 16 bins per chunk
        float wreg[16];
#pragma unroll
        for (int k = 0; k < 16; k++) wreg[k] = w[ch * 16 + k];
#pragma unroll
        for (int r = 0; r < 4; r++) {
            const float4* c4 = (const float4*)(sC + (rg * 4 + r) * SCR_STRIDE);
            float a = 0.0f;
#pragma unroll
            for (int q = 0; q < 4; q++) {
                float4 cv = c4[ch * 4 + q];  // warp-broadcast
                a = fmaf(cv.x, wreg[q * 4 + 0], a);
                a = fmaf(cv.y, wreg[q * 4 + 1], a);
                a = fmaf(cv.z, wreg[q * 4 + 2], a);
                a = fmaf(cv.w, wreg[q * 4 + 3], a);
            }
            if (r == 0) acc0 += a;
            else if (r == 1) acc1 += a;
            else if (r == 2) acc2 += a;
            else acc3 += a;
        }
    }

    const float s0 = sS0[o], s1 = sS1[o], bo = sB[o];
    float accs[4] = {acc0, acc1, acc2, acc3};
#pragma unroll
    for (int r = 0; r < 4; r++) {
        const int rowl = rg * 4 + r;
        const float mnv = sC[rowl * SCR_STRIDE + 128];
        const float wdv = sC[rowl * SCR_STRIDE + 129];
        float res = fmaf(accs[r], 1.0f / 16384.0f,
                         fmaf(mnv, s0, fmaf(wdv, s1, bo)));
        out[(size_t)(r0 + rowl) * N_OUT + o] = res;
    }
}

// ---------------------------------------------------------------------------
extern "C" void kernel_launch(void* const* d_in, const int* in_sizes, int n_in,
                              void* d_out, int out_size) {
    const float* x = (const float*)d_in[0];
    const float* W = (const float*)d_in[1];
    const float* b = (const float*)d_in[2];
    float* out = (float*)d_out;

    const int smemA = 32768 + 32768 + 64 * 4;                        // 65792 B
    const int smemB = (16448 + 192 + ROWS_B * SCR_STRIDE) * 4;       // 75008 B
    cudaFuncSetAttribute(hist_kernel, cudaFuncAttributeMaxDynamicSharedMemorySize, smemA);
    cudaFuncSetAttribute(out_kernel, cudaFuncAttributeMaxDynamicSharedMemorySize, smemB);

    hist_kernel<<<N_ROWS, NT_A, smemA>>>(x);
    out_kernel<<<N_ROWS / ROWS_B, NT_B, smemB>>>(W, b, out);
}

// round 3
// speedup vs baseline: 1.4459x; 1.1260x over previous
#include <cuda_runtime.h>

#define F_DIM 16384
#define N_BINS 128
#define NT 256
#define N_ROWS 4096
#define N_OUT 64

// Prep outputs (allocation-free static scratch)
__device__ float g_wt[N_BINS * N_OUT];   // W[:, :128] transposed to [bin][out]
__device__ float g_s0[N_OUT];            // sum_j W[o][128+j]
__device__ float g_s1[N_OUT];            // sum_j (j/128) W[o][128+j]

__device__ __forceinline__ float f_inf() { return __int_as_float(0x7f800000); }

// ---------------------------------------------------------------------------
// Prep: one CTA per output o. Transpose the counts-half of W to bin-major,
// and reduce the 129 boundary weights to S0/S1.
// ---------------------------------------------------------------------------
__global__ __launch_bounds__(128) void prep_kernel(const float* __restrict__ W) {
    __shared__ float sp0[4], sp1[4];
    const int o = blockIdx.x;
    const int tid = threadIdx.x;

    // Transpose W[o][0..127] -> g_wt[b][o]
    g_wt[tid * N_OUT + o] = W[o * 257 + tid];

    // Boundary sums over j = 0..128 (thread 0 folds in j = 128)
    float wv = W[o * 257 + 128 + tid];
    float s0 = wv;
    float s1 = (float)tid * 0.0078125f * wv;    // exact j/128
    if (tid == 0) {
        float w128 = W[o * 257 + 256];
        s0 += w128;
        s1 += w128;                              // t(128) = 1.0
    }
#pragma unroll
    for (int off = 16; off > 0; off >>= 1) {
        s0 += __shfl_xor_sync(0xFFFFFFFFu, s0, off);
        s1 += __shfl_xor_sync(0xFFFFFFFFu, s1, off);
    }
    if ((tid & 31) == 0) { sp0[tid >> 5] = s0; sp1[tid >> 5] = s1; }
    __syncthreads();
    if (tid == 0) {
        g_s0[o] = sp0[0] + sp0[1] + sp0[2] + sp0[3];
        g_s1[o] = sp1[0] + sp1[1] + sp1[2] + sp1[3];
    }
}

// ---------------------------------------------------------------------------
// Fused kernel: one CTA per row. Row fully register-resident (64 floats).
// Per-thread private u8 histograms (conflict-free layout), 4-way grouped RMW
// with in-group collision merge to break the LDS->IADD->STS serial chain.
// Epilogue computes the 64 outputs for the row (g_wt L1-hot).
// SMEM: [0,32K) hist | +64f red | +128f counts | +256f partials = 34560 B
// -> 3 CTAs/SM (reg-limited at 85 via launch_bounds).
// ---------------------------------------------------------------------------
__global__ __launch_bounds__(NT, 3) void hist_kernel(const float* __restrict__ x,
                                                     const float* __restrict__ bias,
                                                     float* __restrict__ out) {
    extern __shared__ unsigned char smem[];
    unsigned char* s_hist = smem;                         // 32768 B
    float* s_red = (float*)(smem + 32768);                // 64 floats
    float* s_cnt = (float*)(smem + 32768 + 256);          // 128 floats
    float* s_part = (float*)(smem + 32768 + 256 + 512);   // 256 floats

    const int tid = threadIdx.x;
    const int row = blockIdx.x;
    const float4* __restrict__ xr = (const float4*)(x + (size_t)row * F_DIM);

    // ---- Load entire row slice into registers (streaming loads) ----
    float4 rv[16];
#pragma unroll
    for (int i = 0; i < 16; i++) rv[i] = __ldcs(xr + tid + i * NT);

    float mn = f_inf(), mx = -f_inf();
#pragma unroll
    for (int i = 0; i < 16; i++) {
        mn = fminf(mn, fminf(fminf(rv[i].x, rv[i].y), fminf(rv[i].z, rv[i].w)));
        mx = fmaxf(mx, fmaxf(fmaxf(rv[i].x, rv[i].y), fmaxf(rv[i].z, rv[i].w)));
    }
#pragma unroll
    for (int o = 16; o > 0; o >>= 1) {
        mn = fminf(mn, __shfl_xor_sync(0xFFFFFFFFu, mn, o));
        mx = fmaxf(mx, __shfl_xor_sync(0xFFFFFFFFu, mx, o));
    }
    if ((tid & 31) == 0) { s_red[tid >> 5] = mn; s_red[8 + (tid >> 5)] = mx; }

    // Zero histogram (each thread zeroes a contiguous 128 B chunk)
    {
        uint4* hz = (uint4*)(s_hist + tid * 128);
        uint4 z = make_uint4(0u, 0u, 0u, 0u);
#pragma unroll
        for (int i = 0; i < 8; i++) hz[i] = z;
    }
    __syncthreads();

    // Redundant final min/max reduce (no extra sync)
    mn = s_red[0]; mx = s_red[8];
#pragma unroll
    for (int i = 1; i < 8; i++) { mn = fminf(mn, s_red[i]); mx = fmaxf(mx, s_red[8 + i]); }
    const float width = mx - mn;
    const float scale = 128.0f / (width == 0.0f ? 1.0f : width);  // matches jnp where()

    // ---- Bin: counter for (bin, t) at byte s_hist[bin*256 + 4*(t&63) + (t>>6)]
    // bank = t&31 for every lane -> conflict-free byte RMW.
    unsigned char* hbase = s_hist + ((tid & 63) << 2) + (tid >> 6);

#pragma unroll
    for (int i = 0; i < 16; i++) {
        const float4 v = rv[i];
        int b0 = (int)fminf((v.x - mn) * scale, 127.0f);
        int b1 = (int)fminf((v.y - mn) * scale, 127.0f);
        int b2 = (int)fminf((v.z - mn) * scale, 127.0f);
        int b3 = (int)fminf((v.w - mn) * scale, 127.0f);

        // In-group collision merge: live entries have distinct bins,
        // duplicates fold into the earliest entry's multiplicity.
        int n0 = 1, n1 = 1, n2 = 1, n3 = 1;
        if (b1 == b0) { n0 = 2; n1 = 0; }
        if (b2 == b0) { n0++; n2 = 0; }
        else if (n1 && b2 == b1) { n1++; n2 = 0; }
        if (b3 == b0) { n0++; n3 = 0; }
        else if (n1 && b3 == b1) { n1++; n3 = 0; }
        else if (n2 && b3 == b2) { n2++; n3 = 0; }

        unsigned char* p0 = hbase + (b0 << 8);
        unsigned char* p1 = hbase + (b1 << 8);
        unsigned char* p2 = hbase + (b2 << 8);
        unsigned char* p3 = hbase + (b3 << 8);
        // All loads before all stores: 4 LDS in flight -> chain latency /4.
        unsigned int c0 = *p0, c1 = *p1, c2 = *p2, c3 = *p3;
        *p0 = (unsigned char)(c0 + n0);
        if (n1) *p1 = (unsigned char)(c1 + n1);
        if (n2) *p2 = (unsigned char)(c2 + n2);
        if (n3) *p3 = (unsigned char)(c3 + n3);
    }
    __syncthreads();

    // ---- Reduce: bin = tid>>1, each of the pair sums 32 of 64 words.
    // Packed u8 sums in u16 fields (max 64*32 < 65536), lane-rotated banks.
    {
        const unsigned int* h32 = (const unsigned int*)s_hist;
        const int bin = tid >> 1;
        const int base_w = (bin << 6) + ((tid & 1) << 5);
        const int r0 = tid & 31;
        unsigned int lo = 0, hi = 0;
#pragma unroll
        for (int j = 0; j < 32; j++) {
            unsigned int w = h32[base_w + ((r0 + j) & 31)];
            lo += w & 0x00FF00FFu;
            hi += (w >> 8) & 0x00FF00FFu;
        }
        unsigned int s = (lo & 0xFFFFu) + (lo >> 16) + (hi & 0xFFFFu) + (hi >> 16);
        s += __shfl_xor_sync(0xFFFFFFFFu, s, 1);
        if ((tid & 1) == 0) s_cnt[bin] = (float)s;
    }
    __syncthreads();

    // ---- Epilogue: out[row][o] = cnt.Wt[:,o]/F + mn*S0[o] + wd*S1[o] + b[o]
    {
        const int o = tid & 63;
        const int q = tid >> 6;                    // 4 chunks of 32 bins
        const float* wt = g_wt + (q * 32) * N_OUT + o;
        float acc = 0.0f;
#pragma unroll
        for (int j = 0; j < 32; j++)
            acc = fmaf(s_cnt[q * 32 + j], wt[j * N_OUT], acc);  // LDG L1-hot
        s_part[tid] = acc;
    }
    __syncthreads();
    if (tid < 64) {
        float s = (s_part[tid] + s_part[tid + 64]) +
                  (s_part[tid + 128] + s_part[tid + 192]);
        float res = fmaf(s, 1.0f / 16384.0f,
                         fmaf(mn, g_s0[tid], fmaf(width, g_s1[tid], bias[tid])));
        out[(size_t)row * N_OUT + tid] = res;
    }
}

// ---------------------------------------------------------------------------
extern "C" void kernel_launch(void* const* d_in, const int* in_sizes, int n_in,
                              void* d_out, int out_size) {
    const float* x = (const float*)d_in[0];
    const float* W = (const float*)d_in[1];
    const float* b = (const float*)d_in[2];
    float* out = (float*)d_out;

    const int smemA = 32768 + 256 + 512 + 1024;     // 34560 B
    cudaFuncSetAttribute(hist_kernel, cudaFuncAttributeMaxDynamicSharedMemorySize, smemA);

    prep_kernel<<<N_OUT, 128>>>(W);
    hist_kernel<<<N_ROWS, NT, smemA>>>(x, b, out);
}